// round 3
// baseline (speedup 1.0000x reference)
#include <cuda_runtime.h>

#define B_   32
#define S_   512
#define E_   8
#define H_   768
#define KG_  100
#define MH_  1000
#define NROW (B_*E_)     /* 256 */
#define KSPLIT 6
#define KC   167         /* ceil(1000/6), zero-padded */

typedef unsigned long long u64;

// Scratch (device globals — no allocation allowed)
__device__ float g_Hs[NROW * MH_];                       // 256x1000 post-relu hidden
__device__ __align__(16) float g_ENT[KSPLIT][NROW * H_]; // K-split partials of ent

// ---- packed fp32x2 helpers (sm_100+ PTX) ----------------------------------
__device__ __forceinline__ u64 pk2(float a, float b) {
    u64 r; asm("mov.b64 %0, {%1,%2};" : "=l"(r) : "f"(a), "f"(b)); return r;
}
__device__ __forceinline__ u64 fma2(u64 a, u64 b, u64 c) {
    u64 d; asm("fma.rn.f32x2 %0, %1, %2, %3;" : "=l"(d) : "l"(a), "l"(b), "l"(c)); return d;
}
__device__ __forceinline__ float2 up2(u64 v) {
    float2 f; asm("mov.b64 {%0,%1}, %2;" : "=f"(f.x), "=f"(f.y) : "l"(v)); return f;
}

// ---------------------------------------------------------------------------
// K1: Hs = relu(X @ W1 + b1)   X:[256,100]  W1:[100,1000]
// grid (4, 32): x = 256-col group, y = 8-row tile. block 256.
// Rows packed in pairs -> 4 FFMA2 per k per thread.
// ---------------------------------------------------------------------------
__global__ void __launch_bounds__(256) k1_mlp1(const float* __restrict__ X,
                                               const float* __restrict__ W1,
                                               const float* __restrict__ b1) {
    __shared__ u64 xp[4][KG_];   // row pairs duplicated per k
    const int rb = blockIdx.y * 8;
    const int j  = blockIdx.x * 256 + threadIdx.x;

    for (int idx = threadIdx.x; idx < 4 * KG_; idx += 256) {
        int p = idx / KG_, k = idx - p * KG_;
        xp[p][k] = pk2(X[(rb + 2*p) * KG_ + k], X[(rb + 2*p + 1) * KG_ + k]);
    }
    __syncthreads();

    if (j < MH_) {
        const float bj = b1[j];
        u64 acc0 = pk2(bj, bj);
        u64 acc1 = acc0, acc2 = acc0, acc3 = acc0;

        #pragma unroll 10
        for (int k = 0; k < KG_; k++) {
            float w = W1[k * MH_ + j];
            u64 wp = pk2(w, w);
            acc0 = fma2(xp[0][k], wp, acc0);
            acc1 = fma2(xp[1][k], wp, acc1);
            acc2 = fma2(xp[2][k], wp, acc2);
            acc3 = fma2(xp[3][k], wp, acc3);
        }
        float2 a0 = up2(acc0), a1 = up2(acc1), a2 = up2(acc2), a3 = up2(acc3);
        g_Hs[(rb + 0) * MH_ + j] = fmaxf(a0.x, 0.0f);
        g_Hs[(rb + 1) * MH_ + j] = fmaxf(a0.y, 0.0f);
        g_Hs[(rb + 2) * MH_ + j] = fmaxf(a1.x, 0.0f);
        g_Hs[(rb + 3) * MH_ + j] = fmaxf(a1.y, 0.0f);
        g_Hs[(rb + 4) * MH_ + j] = fmaxf(a2.x, 0.0f);
        g_Hs[(rb + 5) * MH_ + j] = fmaxf(a2.y, 0.0f);
        g_Hs[(rb + 6) * MH_ + j] = fmaxf(a3.x, 0.0f);
        g_Hs[(rb + 7) * MH_ + j] = fmaxf(a3.y, 0.0f);
    }
}

// ---------------------------------------------------------------------------
// K2: ENT_part[kz] = Hs[:, kchunk] @ W2[kchunk, :]  (+ b2 folded into kz==0)
// M=256, N=768, K=1000. grid (3, 8, 6). block 256: tx -> 8 cols, ty -> 4 rows.
// Software-pipelined: W2 float4s and hd row for k+1 prefetched into regs.
// ---------------------------------------------------------------------------
__global__ void __launch_bounds__(256, 1) k2_mlp2(const float* __restrict__ W2,
                                                  const float* __restrict__ b2) {
    // hd[k][r] = {h, h} pairs; padded to KC+1 rows for the pipeline prefetch.
    __shared__ u64 hd[KC + 1][34];

    const int cb = blockIdx.x * 256;
    const int rb = blockIdx.y * 32;
    const int kz = blockIdx.z;
    const int kb = kz * KC;
    const int tid = threadIdx.x;

    // Stage 32 x KC slice (coalesced along k), duplicated into pairs; zero-pad.
    #pragma unroll
    for (int r = 0; r < 32; r++) {
        for (int k = tid; k < KC; k += 256) {
            int kk = kb + k;
            float h = (kk < MH_) ? g_Hs[(rb + r) * MH_ + kk] : 0.0f;
            hd[k][r] = pk2(h, h);
        }
    }
    if (tid < 34) hd[KC][tid] = 0ULL;
    __syncthreads();

    const int tx = tid & 31;
    const int ty = tid >> 5;
    const int r0 = ty * 4;
    const int col = cb + tx * 8;

    u64 acc[4][4];   // [row][col-pair]
    if (kz == 0) {
        float4 bv0 = *(const float4*)(b2 + col);
        float4 bv1 = *(const float4*)(b2 + col + 4);
        u64 p0 = pk2(bv0.x, bv0.y), p1 = pk2(bv0.z, bv0.w);
        u64 p2 = pk2(bv1.x, bv1.y), p3 = pk2(bv1.z, bv1.w);
        #pragma unroll
        for (int i = 0; i < 4; i++) { acc[i][0]=p0; acc[i][1]=p1; acc[i][2]=p2; acc[i][3]=p3; }
    } else {
        #pragma unroll
        for (int i = 0; i < 4; i++)
            #pragma unroll
            for (int jj = 0; jj < 4; jj++) acc[i][jj] = 0ULL;
    }

    const float4* __restrict__ W24 = (const float4*)W2;

    // Prologue: k = 0
    int wrow0 = min(kb, MH_ - 1);
    long long wb = ((long long)wrow0 * H_ + col) >> 2;
    float4 w0 = W24[wb], w1 = W24[wb + 1];
    u64 h0 = hd[0][r0 + 0], h1 = hd[0][r0 + 1];
    u64 h2 = hd[0][r0 + 2], h3 = hd[0][r0 + 3];

    #pragma unroll 2
    for (int k = 0; k < KC; k++) {
        // Prefetch k+1 (hd padded; W row clamped in-bounds)
        int wrow = min(kb + k + 1, MH_ - 1);
        long long wbn = ((long long)wrow * H_ + col) >> 2;
        float4 nw0 = W24[wbn], nw1 = W24[wbn + 1];
        u64 nh0 = hd[k + 1][r0 + 0], nh1 = hd[k + 1][r0 + 1];
        u64 nh2 = hd[k + 1][r0 + 2], nh3 = hd[k + 1][r0 + 3];

        u64 wp0 = pk2(w0.x, w0.y), wp1 = pk2(w0.z, w0.w);
        u64 wp2 = pk2(w1.x, w1.y), wp3 = pk2(w1.z, w1.w);

        acc[0][0] = fma2(h0, wp0, acc[0][0]);
        acc[0][1] = fma2(h0, wp1, acc[0][1]);
        acc[0][2] = fma2(h0, wp2, acc[0][2]);
        acc[0][3] = fma2(h0, wp3, acc[0][3]);
        acc[1][0] = fma2(h1, wp0, acc[1][0]);
        acc[1][1] = fma2(h1, wp1, acc[1][1]);
        acc[1][2] = fma2(h1, wp2, acc[1][2]);
        acc[1][3] = fma2(h1, wp3, acc[1][3]);
        acc[2][0] = fma2(h2, wp0, acc[2][0]);
        acc[2][1] = fma2(h2, wp1, acc[2][1]);
        acc[2][2] = fma2(h2, wp2, acc[2][2]);
        acc[2][3] = fma2(h2, wp3, acc[2][3]);
        acc[3][0] = fma2(h3, wp0, acc[3][0]);
        acc[3][1] = fma2(h3, wp1, acc[3][1]);
        acc[3][2] = fma2(h3, wp2, acc[3][2]);
        acc[3][3] = fma2(h3, wp3, acc[3][3]);

        w0 = nw0; w1 = nw1;
        h0 = nh0; h1 = nh1; h2 = nh2; h3 = nh3;
    }

    float* dst = g_ENT[kz];
    #pragma unroll
    for (int i = 0; i < 4; i++) {
        int r = rb + r0 + i;
        float2 a0 = up2(acc[i][0]), a1 = up2(acc[i][1]);
        float2 a2 = up2(acc[i][2]), a3 = up2(acc[i][3]);
        *(float4*)(dst + r * H_ + col)     = make_float4(a0.x, a0.y, a1.x, a1.y);
        *(float4*)(dst + r * H_ + col + 4) = make_float4(a2.x, a2.y, a3.x, a3.y);
    }
}

// ---------------------------------------------------------------------------
// kR: reduce the 6 K-split partials in place into g_ENT[0].
// ---------------------------------------------------------------------------
__global__ void __launch_bounds__(256) kR_reduce() {
    int i = blockIdx.x * 512 + threadIdx.x;
    #pragma unroll
    for (int t = 0; t < 2; t++, i += 256) {
        float4 a = ((const float4*)g_ENT[0])[i];
        #pragma unroll
        for (int p = 1; p < KSPLIT; p++) {
            float4 b = ((const float4*)g_ENT[p])[i];
            a.x += b.x; a.y += b.y; a.z += b.z; a.w += b.w;
        }
        ((float4*)g_ENT[0])[i] = a;
    }
}

// ---------------------------------------------------------------------------
// K3: out[b,s,:] = word_embedding[ids[b,s]] + sum_e mask[b,e,s] * ent[b*E+e,:]
// grid 16384 (one (b,s) row per block), block 192.
// Warp 0 loads the 9 per-row scalars ONCE; ballot -> nonzero bitmask; all
// other threads read 2 smem words. 85% of rows take the pure-copy fast path.
// ---------------------------------------------------------------------------
__global__ void __launch_bounds__(192) k3_fuse(const int*   __restrict__ ids,
                                               const float* __restrict__ mask,
                                               const float* __restrict__ we,
                                               float*       __restrict__ out) {
    const int row = blockIdx.x;
    const int b = row >> 9;
    const int s = row & (S_ - 1);
    const int tid = threadIdx.x;

    __shared__ float    sm[E_];
    __shared__ int      swid;
    __shared__ unsigned sflag;

    if (tid < 32) {
        float m = 0.0f;
        if (tid < E_) {
            m = __ldg(mask + (b * E_ + tid) * S_ + s);
            sm[tid] = m;
        }
        unsigned bal = __ballot_sync(0xffffffffu, m != 0.0f);
        if (tid == 0) sflag = bal;
        if (tid == E_) swid = __ldg(ids + row);
    }
    __syncthreads();

    const long long wid = swid;
    float4 v = ((const float4*)we)[wid * (H_ / 4) + tid];
    const unsigned flag = sflag;

    if (flag) {
        #pragma unroll
        for (int e = 0; e < E_; e++) {
            if (flag & (1u << e)) {
                float m = sm[e];
                float4 p = ((const float4*)g_ENT[0])[(b * E_ + e) * (H_ / 4) + tid];
                v.x = fmaf(m, p.x, v.x);
                v.y = fmaf(m, p.y, v.y);
                v.z = fmaf(m, p.z, v.z);
                v.w = fmaf(m, p.w, v.w);
            }
        }
    }

    ((float4*)out)[(long long)row * (H_ / 4) + tid] = v;
}

// ---------------------------------------------------------------------------
extern "C" void kernel_launch(void* const* d_in, const int* in_sizes, int n_in,
                              void* d_out, int out_size) {
    const int*   ids  = (const int*)  d_in[0];   // input_ids        [32,512]
    const float* X    = (const float*)d_in[1];   // entity_embeddings[32,8,100]
    const float* msk  = (const float*)d_in[2];   // entity_mask      [32,8,512]
    const float* we   = (const float*)d_in[3];   // word_embedding   [30522,768]
    const float* W1   = (const float*)d_in[4];   // [100,1000]
    const float* b1   = (const float*)d_in[5];   // [1000]
    const float* W2   = (const float*)d_in[6];   // [1000,768]
    const float* b2   = (const float*)d_in[7];   // [768]
    float* out = (float*)d_out;                  // [32,512,768]

    k1_mlp1<<<dim3(4, 32), 256>>>(X, W1, b1);
    k2_mlp2<<<dim3(3, 8, KSPLIT), 256>>>(W2, b2);
    kR_reduce<<<96, 256>>>();
    k3_fuse<<<B_ * S_, 192>>>(ids, msk, we, out);
}